// round 13
// baseline (speedup 1.0000x reference)
#include <cuda_runtime.h>
#include <cuda_fp16.h>
#include <math.h>
#include <stdint.h>

#define FDIM 64
#define HID  128
#define N_ATOMS_MAX 100000
#define N_BONDS_MAX 800000

// ---------------- device scratch (no allocs allowed) ----------------
__device__ float g_bond_sum[FDIM];
__device__ float g_atom_sum[FDIM];
__device__ __align__(16) unsigned short g_atom_h[(size_t)N_ATOMS_MAX * FDIM]; // fp16 atom feats
__device__ __align__(16) unsigned short g_agg_h [(size_t)N_ATOMS_MAX * FDIM]; // fp16 agg
__device__ __align__(16) unsigned short g_bond_h[(size_t)N_BONDS_MAX * FDIM]; // fp16 updated bonds
__device__ __align__(16) unsigned short g_h_dev[FDIM];                        // fp16 global feats
// pre-transposed fp16 weight images: W^T stored [N][K] row-major
__device__ __align__(16) unsigned short wb1_img[HID * 4 * FDIM];   // [128][256]
__device__ __align__(16) unsigned short wb2_img[FDIM * HID];       // [64][128]
__device__ __align__(16) unsigned short wa1_img[HID * 4 * FDIM];
__device__ __align__(16) unsigned short wa2_img[FDIM * HID];

// ---------------- helpers ----------------
__device__ __forceinline__ float softplus_f(float x) {
    float t = __expf(-fabsf(x));
    return fmaxf(x, 0.f) + __logf(1.f + t);
}
__device__ __forceinline__ uint32_t pack_h2(float a, float b) {
    __half2 h = __floats2half2_rn(a, b);
    return *(uint32_t*)&h;
}
__device__ __forceinline__ uint32_t smem_u32(const void* p) {
    uint32_t a;
    asm("{ .reg .u64 t; cvta.to.shared.u64 t, %1; cvt.u32.u64 %0, t; }"
        : "=r"(a) : "l"(p));
    return a;
}
__device__ __forceinline__ void ldm_x4(uint32_t (&r)[4], uint32_t addr) {
    asm volatile("ldmatrix.sync.aligned.m8n8.x4.shared.b16 {%0,%1,%2,%3}, [%4];"
                 : "=r"(r[0]), "=r"(r[1]), "=r"(r[2]), "=r"(r[3]) : "r"(addr));
}
__device__ __forceinline__ void mma16816(float (&d)[4], const uint32_t (&a)[4],
                                         uint32_t b0, uint32_t b1) {
    asm volatile("mma.sync.aligned.m16n8k16.row.col.f32.f16.f16.f32 "
                 "{%0,%1,%2,%3}, {%4,%5,%6,%7}, {%8,%9}, {%0,%1,%2,%3};"
                 : "+f"(d[0]), "+f"(d[1]), "+f"(d[2]), "+f"(d[3])
                 : "r"(a[0]), "r"(a[1]), "r"(a[2]), "r"(a[3]), "r"(b0), "r"(b1));
}
__device__ __forceinline__ void cpa16(uint32_t dst, const void* src) {
    asm volatile("cp.async.ca.shared.global [%0], [%1], 16;"
                 :: "r"(dst), "l"(src));
}
__device__ __forceinline__ void cpa_wait_all() {
    asm volatile("cp.async.wait_all;" ::: "memory");
}

// ---------------- init ----------------
__global__ void init_kernel() {
    int t = threadIdx.x;
    if (t < FDIM) { g_bond_sum[t] = 0.f; g_atom_sum[t] = 0.f; }
}

// ---------------- weight transpose + fp16 convert ----------------
__global__ void prep_weights(const float* __restrict__ W1, const float* __restrict__ W2,
                             unsigned short* __restrict__ img1,
                             unsigned short* __restrict__ img2) {
    int idx = blockIdx.x * blockDim.x + threadIdx.x;
    if (idx < HID * 4 * FDIM) {                 // W1^T [128][256]
        int n = idx >> 8, k = idx & 255;
        __half h = __float2half_rn(W1[(size_t)k * HID + n]);
        img1[idx] = *(unsigned short*)&h;
    } else if (idx < HID * 4 * FDIM + FDIM * HID) {  // W2^T [64][128]
        int t = idx - HID * 4 * FDIM;
        int n = t >> 7, k = t & 127;
        __half h = __float2half_rn(W2[(size_t)k * FDIM + n]);
        img2[t] = *(unsigned short*)&h;
    }
}

// ---------------- atom features + gfeat -> fp16 ----------------
__global__ void prep_atom(const float* __restrict__ atom_f,
                          const float* __restrict__ gfeat, int n4) {
    int idx = blockIdx.x * blockDim.x + threadIdx.x;
    if (idx < n4) {
        float4 v = ((const float4*)atom_f)[idx];
        uint2 o = make_uint2(pack_h2(v.x, v.y), pack_h2(v.z, v.w));
        ((uint2*)g_atom_h)[idx] = o;
    }
    if (blockIdx.x == 0 && threadIdx.x < 16) {
        float4 v = ((const float4*)gfeat)[threadIdx.x];
        ((uint2*)g_h_dev)[threadIdx.x] = make_uint2(pack_h2(v.x, v.y), pack_h2(v.z, v.w));
    }
}

// ---------------- SMEM layout (bytes) ----------------
static constexpr int ASTRIDE = 528;   // 256+8 halves
static constexpr int HSTRIDE = 272;   // 128+8 halves
static constexpr int SM_A  = 0;                          // 128 rows (4 groups x 32)
static constexpr int SM_W1 = SM_A + 128 * ASTRIDE;       // 67584
static constexpr int SM_H  = SM_W1 + 128 * ASTRIDE;      // 135168
static constexpr int SM_W2 = SM_H + 128 * HSTRIDE;       // 169984
static constexpr int SM_B1 = SM_W2 + 64 * HSTRIDE;       // 187392
static constexpr int SM_B2 = SM_B1 + 512;                // 187904
static constexpr int SM_CS = SM_B2 + 256;                // 188160
static constexpr int SM_RES = SM_CS + 256;               // 188416 (128 rows x 256B fp32)
static constexpr int SMEM_SZ = SM_RES + 128 * 256;       // 221184

// ---------------- persistent fused 2-layer MLP (mma.sync) ----------------
// 4 independent 128-thread groups per CTA; each owns a 32-row tile stream.
// MODE 0 (bonds): comb = [atom_h[i], atom_h[j], f16(bond_f[row]), g_h]
// MODE 1 (atoms): comb = [atom_h[row], agg_h[row], atom_h[row], g_h]
template <int MODE>
__global__ __launch_bounds__(512, 1)
void mlp_tc(const float* __restrict__ resid_glob,   // MODE1: atom_f; MODE0: bond_f
            const float* __restrict__ b1, const float* __restrict__ b2,
            const int*   __restrict__ ab_idx,       // MODE0 only
            const unsigned short* __restrict__ w1img,
            const unsigned short* __restrict__ w2img,
            float* __restrict__ outp,
            int n_rows)
{
    extern __shared__ __align__(16) char smem[];
    const uint32_t sb = smem_u32(smem);
    float* bias1  = (float*)(smem + SM_B1);
    float* bias2  = (float*)(smem + SM_B2);
    float* colsum = (float*)(smem + SM_CS);

    const int tid = threadIdx.x, wid = tid >> 5, lane = tid & 31;
    const int gid = wid >> 2;            // group 0..3
    const int warp_n = wid & 3;          // n-column split within group
    const int tg = tid & 127;            // thread-in-group
    const int n_tiles = (n_rows + 31) >> 5;   // 32-row tiles

    // ---- one-time staging: weights (padded stride), biases, colsum ----
    for (int i = tid; i < 4096; i += 512) {               // W1T: 128 rows x 32 uint4
        int r = i >> 5, c = i & 31;
        *(uint4*)(smem + SM_W1 + r * ASTRIDE + c * 16) = ((const uint4*)w1img)[i];
    }
    for (int i = tid; i < 1024; i += 512) {               // W2T: 64 rows x 16 uint4
        int r = i >> 4, c = i & 15;
        *(uint4*)(smem + SM_W2 + r * HSTRIDE + c * 16) = ((const uint4*)w2img)[i];
    }
    if (tid < HID)  bias1[tid] = b1[tid];
    if (tid < FDIM) { bias2[tid] = b2[tid]; colsum[tid] = 0.f; }

    // gather thread mapping: 4 threads per row, 32 rows per group
    const int grow_r = tg >> 2, qs = tg & 3;

    // ldmatrix lane-address components
    const uint32_t aLane1 = (uint32_t)((lane & 15) * ASTRIDE + (lane >> 4) * 16);
    const uint32_t aLane2 = (uint32_t)((lane & 15) * HSTRIDE + (lane >> 4) * 16);
    const uint32_t bN = (uint32_t)((lane & 7) + ((lane >> 4) << 3));
    const uint32_t bK = (uint32_t)(((lane >> 3) & 1) * 16);
    const uint32_t aBase1 = sb + SM_A + (uint32_t)(gid * 32) * ASTRIDE + aLane1;
    const uint32_t bBase1 = sb + SM_W1 + (uint32_t)(warp_n * 32 + bN) * ASTRIDE + bK;
    const uint32_t aBase2 = sb + SM_H + (uint32_t)(gid * 32) * HSTRIDE + aLane2;
    const uint32_t bBase2 = sb + SM_W2 + (uint32_t)(warp_n * 16 + bN) * HSTRIDE + bK;

    float ls[2][2] = {{0.f, 0.f}, {0.f, 0.f}};   // per-thread running column sums

    // async gather of fp16 A segments for one 32-row tile (group-local)
    auto gather_async = [&](int t) {
        int gr = t * 32 + grow_r;
        int grc = gr < n_rows ? gr : n_rows - 1;
        const uint32_t dstrow = sb + SM_A + (uint32_t)(gid * 32 + grow_r) * ASTRIDE;
        if (MODE == 0) {
            if (qs == 0) {
                const char* src = (const char*)(g_atom_h + (size_t)ab_idx[2 * grc] * FDIM);
#pragma unroll
                for (int q = 0; q < 8; q++) cpa16(dstrow + q * 16, src + q * 16);
            } else if (qs == 1) {
                const char* src = (const char*)(g_atom_h + (size_t)ab_idx[2 * grc + 1] * FDIM);
#pragma unroll
                for (int q = 0; q < 8; q++) cpa16(dstrow + 128 + q * 16, src + q * 16);
            } else if (qs == 2) {
#pragma unroll
                for (int q = 0; q < 4; q++) cpa16(dstrow + 384 + q * 16, (const char*)g_h_dev + q * 16);
            } else {
#pragma unroll
                for (int q = 0; q < 4; q++) cpa16(dstrow + 448 + q * 16, (const char*)g_h_dev + 64 + q * 16);
            }
        } else {
            const char* arow = (const char*)(g_atom_h + (size_t)grc * FDIM);
            if (qs == 0) {
#pragma unroll
                for (int q = 0; q < 8; q++) cpa16(dstrow + q * 16, arow + q * 16);
            } else if (qs == 1) {
                const char* src = (const char*)(g_agg_h + (size_t)grc * FDIM);
#pragma unroll
                for (int q = 0; q < 8; q++) cpa16(dstrow + 128 + q * 16, src + q * 16);
            } else if (qs == 2) {
#pragma unroll
                for (int q = 0; q < 8; q++) cpa16(dstrow + 256 + q * 16, arow + q * 16);
            } else {
#pragma unroll
                for (int q = 0; q < 8; q++) cpa16(dstrow + 384 + q * 16, (const char*)g_h_dev + q * 16);
            }
        }
    };

    // register prefetch of the fp32 residual row quarter (both modes)
    float4 pb0, pb1, pb2, pb3;
    auto load_resid = [&](int t) {
        int gr = t * 32 + grow_r;
        int grc = gr < n_rows ? gr : n_rows - 1;
        const float4* bs = (const float4*)(resid_glob + (size_t)grc * FDIM) + qs * 4;
        pb0 = bs[0]; pb1 = bs[1]; pb2 = bs[2]; pb3 = bs[3];
    };

    const int stride = (int)gridDim.x * 4;
    int tile = blockIdx.x * 4 + gid;
    if (tile < n_tiles) { gather_async(tile); load_resid(tile); }
    __syncthreads();                       // weights/bias staged (CTA-wide, once)

    for (; tile < n_tiles; tile += stride) {
        const int row_base = tile * 32;

        // ---- commit prefetched residual row: fp32 -> RES (and MODE0: fp16 -> A seg2)
        {
            if (MODE == 0) {
                char* adst = smem + SM_A + (gid * 32 + grow_r) * ASTRIDE + 256 + qs * 32;
                ((uint4*)adst)[0] = make_uint4(pack_h2(pb0.x, pb0.y), pack_h2(pb0.z, pb0.w),
                                               pack_h2(pb1.x, pb1.y), pack_h2(pb1.z, pb1.w));
                ((uint4*)adst)[1] = make_uint4(pack_h2(pb2.x, pb2.y), pack_h2(pb2.z, pb2.w),
                                               pack_h2(pb3.x, pb3.y), pack_h2(pb3.z, pb3.w));
            }
            float4* rdst = (float4*)(smem + SM_RES + (gid * 32 + grow_r) * 256) + qs * 4;
            rdst[0] = pb0; rdst[1] = pb1; rdst[2] = pb2; rdst[3] = pb3;
        }
        cpa_wait_all();
        asm volatile("bar.sync %0, 128;" :: "r"(gid + 1) : "memory");   // A/RES ready

        // ---- layer 1: c1 (32 rows x 32 cols per warp) ----
        float c1[2][4][4];
#pragma unroll
        for (int mi = 0; mi < 2; mi++)
#pragma unroll
            for (int nb = 0; nb < 4; nb++)
#pragma unroll
                for (int j = 0; j < 4; j++) c1[mi][nb][j] = 0.f;

#pragma unroll
        for (int k0 = 0; k0 < 256; k0 += 16) {
            uint32_t a0[4], a1[4];
            ldm_x4(a0, aBase1 + k0 * 2);
            ldm_x4(a1, aBase1 + 16 * ASTRIDE + k0 * 2);
#pragma unroll
            for (int g = 0; g < 2; g++) {
                uint32_t bf[4];
                ldm_x4(bf, bBase1 + (uint32_t)(g * 16) * ASTRIDE + k0 * 2);
                mma16816(c1[0][2 * g],     a0, bf[0], bf[1]);
                mma16816(c1[0][2 * g + 1], a0, bf[2], bf[3]);
                mma16816(c1[1][2 * g],     a1, bf[0], bf[1]);
                mma16816(c1[1][2 * g + 1], a1, bf[2], bf[3]);
            }
        }

        // ---- epilogue 1: bias + softplus -> fp16 H (group slice) ----
        {
            const int r0 = lane >> 2;
            const int cb = warp_n * 32 + (lane & 3) * 2;
#pragma unroll
            for (int mi = 0; mi < 2; mi++) {
#pragma unroll
                for (int nb = 0; nb < 4; nb++) {
                    int col = cb + nb * 8;
                    float b0v = bias1[col], b1v = bias1[col + 1];
                    uint32_t p0 = pack_h2(softplus_f(c1[mi][nb][0] + b0v),
                                          softplus_f(c1[mi][nb][1] + b1v));
                    uint32_t p1 = pack_h2(softplus_f(c1[mi][nb][2] + b0v),
                                          softplus_f(c1[mi][nb][3] + b1v));
                    int row = gid * 32 + mi * 16 + r0;
                    *(uint32_t*)(smem + SM_H + row * HSTRIDE + col * 2) = p0;
                    *(uint32_t*)(smem + SM_H + (row + 8) * HSTRIDE + col * 2) = p1;
                }
            }
        }
        asm volatile("bar.sync %0, 128;" :: "r"(gid + 1) : "memory");   // H ready, A free

        // ---- prefetch next tile (overlaps MMA2 + epilogue2) ----
        if (tile + stride < n_tiles) { gather_async(tile + stride); load_resid(tile + stride); }

        // ---- layer 2: c2 (32 rows x 16 cols per warp) ----
        float c2[2][2][4];
#pragma unroll
        for (int mi = 0; mi < 2; mi++)
#pragma unroll
            for (int nb = 0; nb < 2; nb++)
#pragma unroll
                for (int j = 0; j < 4; j++) c2[mi][nb][j] = 0.f;

#pragma unroll
        for (int k0 = 0; k0 < 128; k0 += 16) {
            uint32_t a0[4], a1[4], bf[4];
            ldm_x4(a0, aBase2 + k0 * 2);
            ldm_x4(a1, aBase2 + 16 * HSTRIDE + k0 * 2);
            ldm_x4(bf, bBase2 + k0 * 2);
            mma16816(c2[0][0], a0, bf[0], bf[1]);
            mma16816(c2[0][1], a0, bf[2], bf[3]);
            mma16816(c2[1][0], a1, bf[0], bf[1]);
            mma16816(c2[1][1], a1, bf[2], bf[3]);
        }

        // All warps in the group must finish READING H (layer-2 A operand)
        // before anyone overwrites H with the fp16 output mirror below.
        asm volatile("bar.sync %0, 128;" :: "r"(gid + 1) : "memory");

        // ---- epilogue 2: bias + residual; stage o into RES (fp32) + H (fp16) ----
        {
            const int cb2 = warp_n * 16 + (lane & 3) * 2;
#pragma unroll
            for (int mi = 0; mi < 2; mi++) {
#pragma unroll
                for (int half = 0; half < 2; half++) {
                    int row = mi * 16 + half * 8 + (lane >> 2);
                    bool valid = (row_base + row) < n_rows;
#pragma unroll
                    for (int nb = 0; nb < 2; nb++) {
                        int col = cb2 + nb * 8;
                        float* rp = (float*)(smem + SM_RES + (gid * 32 + row) * 256 + col * 4);
                        float v0 = c2[mi][nb][half * 2 + 0] + bias2[col]     + rp[0];
                        float v1 = c2[mi][nb][half * 2 + 1] + bias2[col + 1] + rp[1];
                        rp[0] = v0; rp[1] = v1;
                        if (MODE == 0)
                            *(uint32_t*)(smem + SM_H + (gid * 32 + row) * HSTRIDE + col * 2) =
                                pack_h2(v0, v1);
                        if (valid) { ls[nb][0] += v0; ls[nb][1] += v1; }
                    }
                }
            }
        }
        asm volatile("bar.sync %0, 128;" :: "r"(gid + 1) : "memory");   // staged

        // ---- coalesced writeback: 64B fp32 per thread (+32B fp16 MODE0) ----
        {
            int row = grow_r;
            int grow = row_base + row;
            if (grow < n_rows) {
                const float4* src = (const float4*)(smem + SM_RES + (gid * 32 + row) * 256) + qs * 4;
                float4* dst = (float4*)(outp + (size_t)grow * FDIM) + qs * 4;
                dst[0] = src[0]; dst[1] = src[1]; dst[2] = src[2]; dst[3] = src[3];
                if (MODE == 0) {
                    const uint4* hs = (const uint4*)(smem + SM_H + (gid * 32 + row) * HSTRIDE + qs * 32);
                    uint4* hd = (uint4*)((char*)g_bond_h + (size_t)grow * 128 + qs * 32);
                    hd[0] = hs[0]; hd[1] = hs[1];
                }
            }
        }
        asm volatile("bar.sync %0, 128;" :: "r"(gid + 1) : "memory");   // RES/H reusable
    }

    // ---- flush column sums ----
#pragma unroll
    for (int nb = 0; nb < 2; nb++) {
        int col = warp_n * 16 + (lane & 3) * 2 + nb * 8;
        atomicAdd(&colsum[col],     ls[nb][0]);
        atomicAdd(&colsum[col + 1], ls[nb][1]);
    }
    __syncthreads();
    if (tid < FDIM) {
        float* gsum = (MODE == 0) ? g_bond_sum : g_atom_sum;
        atomicAdd(&gsum[tid], colsum[tid]);
    }
}

// ---------------- bond -> atom masked mean aggregation (fp16 in/out) -------
__global__ void agg_kernel(const int* __restrict__ bai, int n_atoms, int max_deg)
{
    int warp = (blockIdx.x * blockDim.x + threadIdx.x) >> 5;
    int lane = threadIdx.x & 31;
    if (warp >= n_atoms) return;
    int myidx = (lane < max_deg) ? bai[(size_t)warp * max_deg + lane] : -1;
    unsigned mb = __ballot_sync(0xffffffffu, myidx >= 0);
    int cnt = __popc(mb);
    float sx = 0.f, sy = 0.f;
#pragma unroll
    for (int d = 0; d < 32; d += 8) {
        if (d >= max_deg) break;
        int i0 = __shfl_sync(0xffffffffu, myidx, d + 0);
        int i1 = __shfl_sync(0xffffffffu, myidx, d + 1);
        int i2 = __shfl_sync(0xffffffffu, myidx, d + 2);
        int i3 = __shfl_sync(0xffffffffu, myidx, d + 3);
        int i4 = __shfl_sync(0xffffffffu, myidx, d + 4);
        int i5 = __shfl_sync(0xffffffffu, myidx, d + 5);
        int i6 = __shfl_sync(0xffffffffu, myidx, d + 6);
        int i7 = __shfl_sync(0xffffffffu, myidx, d + 7);
        int ids[8] = {i0, i1, i2, i3, i4, i5, i6, i7};
#pragma unroll
        for (int q = 0; q < 8; q++) {
            if (d + q < max_deg && ids[q] >= 0) {
                uint32_t u = ((const uint32_t*)g_bond_h)[(size_t)ids[q] * 32 + lane];
                float2 v = __half22float2(*(__half2*)&u);
                sx += v.x; sy += v.y;
            }
        }
    }
    float inv = 1.f / fmaxf((float)cnt, 1.f);
    ((uint32_t*)g_agg_h)[(size_t)warp * 32 + lane] = pack_h2(sx * inv, sy * inv);
}

// ---------------- global MLP ----------------
__global__ void global_kernel(const float* __restrict__ gfeat,
                              const float* __restrict__ Wg1, const float* __restrict__ bg1,
                              const float* __restrict__ Wg2, const float* __restrict__ bg2,
                              float* __restrict__ outg,
                              float n_atoms_f, float n_bonds_f)
{
    __shared__ float comb[3 * FDIM];
    __shared__ float h[HID];
    int t = threadIdx.x;  // 192 threads
    if (t < FDIM)            comb[t] = g_atom_sum[t] / n_atoms_f;
    else if (t < 2 * FDIM)   comb[t] = g_bond_sum[t - FDIM] / n_bonds_f;
    else if (t < 3 * FDIM)   comb[t] = gfeat[t - 2 * FDIM];
    __syncthreads();
    if (t < HID) {
        float a = bg1[t];
#pragma unroll 4
        for (int k = 0; k < 3 * FDIM; k++) a += comb[k] * Wg1[(size_t)k * HID + t];
        h[t] = softplus_f(a);
    }
    __syncthreads();
    if (t < FDIM) {
        float a = bg2[t] + gfeat[t];
#pragma unroll 4
        for (int k = 0; k < HID; k++) a += h[k] * Wg2[(size_t)k * FDIM + t];
        outg[t] = a;
    }
}

// ---------------- launch ----------------
extern "C" void kernel_launch(void* const* d_in, const int* in_sizes, int n_in,
                              void* d_out, int out_size)
{
    const float* atom_f = (const float*)d_in[0];
    const float* bond_f = (const float*)d_in[1];
    const float* gfeat  = (const float*)d_in[2];
    const float* Wb1 = (const float*)d_in[3];
    const float* bb1 = (const float*)d_in[4];
    const float* Wb2 = (const float*)d_in[5];
    const float* bb2 = (const float*)d_in[6];
    const float* Wa1 = (const float*)d_in[7];
    const float* ba1 = (const float*)d_in[8];
    const float* Wa2 = (const float*)d_in[9];
    const float* ba2 = (const float*)d_in[10];
    const float* Wg1 = (const float*)d_in[11];
    const float* bg1 = (const float*)d_in[12];
    const float* Wg2 = (const float*)d_in[13];
    const float* bg2 = (const float*)d_in[14];
    const int* ab_idx = (const int*)d_in[15];
    const int* ba_idx = (const int*)d_in[16];

    const int n_atoms = in_sizes[0] / FDIM;
    const int n_bonds = in_sizes[1] / FDIM;
    const int max_deg = in_sizes[16] / n_atoms;

    float* out       = (float*)d_out;
    float* out_atoms = out;
    float* out_bonds = out + (size_t)n_atoms * FDIM;
    float* out_glob  = out + (size_t)n_atoms * FDIM + (size_t)n_bonds * FDIM;

    cudaFuncSetAttribute(mlp_tc<0>, cudaFuncAttributeMaxDynamicSharedMemorySize, SMEM_SZ);
    cudaFuncSetAttribute(mlp_tc<1>, cudaFuncAttributeMaxDynamicSharedMemorySize, SMEM_SZ);

    unsigned short *pwb1, *pwb2, *pwa1, *pwa2;
    cudaGetSymbolAddress((void**)&pwb1, wb1_img);
    cudaGetSymbolAddress((void**)&pwb2, wb2_img);
    cudaGetSymbolAddress((void**)&pwa1, wa1_img);
    cudaGetSymbolAddress((void**)&pwa2, wa2_img);

    int nsm = 148;
    cudaDeviceGetAttribute(&nsm, cudaDevAttrMultiProcessorCount, 0);

    init_kernel<<<1, 128>>>();

    const int prep_elems = HID * 4 * FDIM + FDIM * HID;
    prep_weights<<<(prep_elems + 255) / 256, 256>>>(Wb1, Wb2, pwb1, pwb2);
    prep_weights<<<(prep_elems + 255) / 256, 256>>>(Wa1, Wa2, pwa1, pwa2);

    const int n4 = n_atoms * (FDIM / 4);
    prep_atom<<<(n4 + 255) / 256, 256>>>(atom_f, gfeat, n4);

    const int bond_tiles32 = (n_bonds + 31) / 32;
    int grid0 = nsm < (bond_tiles32 + 3) / 4 ? nsm : (bond_tiles32 + 3) / 4;
    if (grid0 < 1) grid0 = 1;
    mlp_tc<0><<<grid0, 512, SMEM_SZ>>>(
        bond_f, bb1, bb2, ab_idx, pwb1, pwb2, out_bonds, n_bonds);

    const int agg_blocks = ((n_atoms * 32) + 255) / 256;
    agg_kernel<<<agg_blocks, 256>>>(ba_idx, n_atoms, max_deg);

    const int atom_tiles32 = (n_atoms + 31) / 32;
    int grid1 = nsm < (atom_tiles32 + 3) / 4 ? nsm : (atom_tiles32 + 3) / 4;
    if (grid1 < 1) grid1 = 1;
    mlp_tc<1><<<grid1, 512, SMEM_SZ>>>(
        atom_f, ba1, ba2, nullptr, pwa1, pwa2, out_atoms, n_atoms);

    global_kernel<<<1, 192>>>(gfeat, Wg1, bg1, Wg2, bg2, out_glob,
                              (float)n_atoms, (float)n_bonds);
}

// round 15
// speedup vs baseline: 1.1757x; 1.1757x over previous
#include <cuda_runtime.h>
#include <cuda_fp16.h>
#include <math.h>
#include <stdint.h>

#define FDIM 64
#define HID  128
#define N_ATOMS_MAX 100000
#define N_BONDS_MAX 800000

// ---------------- device scratch (no allocs allowed) ----------------
__device__ float g_bond_sum[FDIM];
__device__ float g_atom_sum[FDIM];
__device__ __align__(16) unsigned short g_atom_h[(size_t)N_ATOMS_MAX * FDIM]; // fp16 atom feats
__device__ __align__(16) unsigned short g_agg_h [(size_t)N_ATOMS_MAX * FDIM]; // fp16 agg
__device__ __align__(16) unsigned short g_bond_h[(size_t)N_BONDS_MAX * FDIM]; // fp16 updated bonds
__device__ __align__(16) unsigned short g_h_dev[FDIM];                        // fp16 global feats
// pre-transposed fp16 weight images: W^T stored [N][K] row-major
__device__ __align__(16) unsigned short wb1_img[HID * 4 * FDIM];   // [128][256]
__device__ __align__(16) unsigned short wb2_img[FDIM * HID];       // [64][128]
__device__ __align__(16) unsigned short wa1_img[HID * 4 * FDIM];
__device__ __align__(16) unsigned short wa2_img[FDIM * HID];

// ---------------- helpers ----------------
__device__ __forceinline__ float softplus_f(float x) {
    float t = __expf(-fabsf(x));
    return fmaxf(x, 0.f) + __logf(1.f + t);
}
__device__ __forceinline__ uint32_t pack_h2(float a, float b) {
    __half2 h = __floats2half2_rn(a, b);
    return *(uint32_t*)&h;
}
__device__ __forceinline__ uint32_t smem_u32(const void* p) {
    uint32_t a;
    asm("{ .reg .u64 t; cvta.to.shared.u64 t, %1; cvt.u32.u64 %0, t; }"
        : "=r"(a) : "l"(p));
    return a;
}
__device__ __forceinline__ void ldm_x4(uint32_t (&r)[4], uint32_t addr) {
    asm volatile("ldmatrix.sync.aligned.m8n8.x4.shared.b16 {%0,%1,%2,%3}, [%4];"
                 : "=r"(r[0]), "=r"(r[1]), "=r"(r[2]), "=r"(r[3]) : "r"(addr));
}
__device__ __forceinline__ void mma16816(float (&d)[4], const uint32_t (&a)[4],
                                         uint32_t b0, uint32_t b1) {
    asm volatile("mma.sync.aligned.m16n8k16.row.col.f32.f16.f16.f32 "
                 "{%0,%1,%2,%3}, {%4,%5,%6,%7}, {%8,%9}, {%0,%1,%2,%3};"
                 : "+f"(d[0]), "+f"(d[1]), "+f"(d[2]), "+f"(d[3])
                 : "r"(a[0]), "r"(a[1]), "r"(a[2]), "r"(a[3]), "r"(b0), "r"(b1));
}
__device__ __forceinline__ void cpa16(uint32_t dst, const void* src) {
    asm volatile("cp.async.ca.shared.global [%0], [%1], 16;"
                 :: "r"(dst), "l"(src));
}
__device__ __forceinline__ void cpa_wait_all() {
    asm volatile("cp.async.wait_all;" ::: "memory");
}

// ---------------- init ----------------
__global__ void init_kernel() {
    int t = threadIdx.x;
    if (t < FDIM) { g_bond_sum[t] = 0.f; g_atom_sum[t] = 0.f; }
}

// ---------------- weight transpose + fp16 convert ----------------
__global__ void prep_weights(const float* __restrict__ W1, const float* __restrict__ W2,
                             unsigned short* __restrict__ img1,
                             unsigned short* __restrict__ img2) {
    int idx = blockIdx.x * blockDim.x + threadIdx.x;
    if (idx < HID * 4 * FDIM) {                 // W1^T [128][256]
        int n = idx >> 8, k = idx & 255;
        __half h = __float2half_rn(W1[(size_t)k * HID + n]);
        img1[idx] = *(unsigned short*)&h;
    } else if (idx < HID * 4 * FDIM + FDIM * HID) {  // W2^T [64][128]
        int t = idx - HID * 4 * FDIM;
        int n = t >> 7, k = t & 127;
        __half h = __float2half_rn(W2[(size_t)k * FDIM + n]);
        img2[t] = *(unsigned short*)&h;
    }
}

// ---------------- atom features + gfeat -> fp16 ----------------
__global__ void prep_atom(const float* __restrict__ atom_f,
                          const float* __restrict__ gfeat, int n4) {
    int idx = blockIdx.x * blockDim.x + threadIdx.x;
    if (idx < n4) {
        float4 v = ((const float4*)atom_f)[idx];
        uint2 o = make_uint2(pack_h2(v.x, v.y), pack_h2(v.z, v.w));
        ((uint2*)g_atom_h)[idx] = o;
    }
    if (blockIdx.x == 0 && threadIdx.x < 16) {
        float4 v = ((const float4*)gfeat)[threadIdx.x];
        ((uint2*)g_h_dev)[threadIdx.x] = make_uint2(pack_h2(v.x, v.y), pack_h2(v.z, v.w));
    }
}

// ---------------- SMEM layout (bytes) ----------------
static constexpr int ASTRIDE = 528;   // 256+8 halves
static constexpr int HSTRIDE = 272;   // 128+8 halves
static constexpr int SM_A  = 0;                          // 128 rows (8 warps x 16)
static constexpr int SM_W1 = SM_A + 128 * ASTRIDE;       // 67584
static constexpr int SM_W2 = SM_W1 + 128 * ASTRIDE;      // 135168 (64 rows x HSTRIDE)
static constexpr int SM_B1 = SM_W2 + 64 * HSTRIDE;       // 152576
static constexpr int SM_B2 = SM_B1 + 512;                // 153088
static constexpr int SM_CS = SM_B2 + 256;                // 153344
static constexpr int SM_RES = SM_CS + 256;               // 153600 (128 rows x 256B fp32)
static constexpr int SMEM_SZ = SM_RES + 128 * 256;       // 186368

// ---------------- persistent fused 2-layer MLP (mma.sync) ----------------
// Fully warp-independent: each warp owns a 16-row tile stream, computes the
// entire layer-1 N=128, keeps the softplus'd hidden IN REGISTERS (D-fragment
// of layer1 == A-fragment of layer2), then layer-2 N=64. No CTA/group
// barriers in the main loop — only __syncwarp.
// MODE 0 (bonds): comb = [atom_h[i], atom_h[j], f16(bond_f[row]), g_h]
// MODE 1 (atoms): comb = [atom_h[row], agg_h[row], atom_h[row], g_h]
template <int MODE>
__global__ __launch_bounds__(256, 1)
void mlp_tc(const float* __restrict__ resid_glob,   // MODE1: atom_f; MODE0: bond_f
            const float* __restrict__ b1, const float* __restrict__ b2,
            const int*   __restrict__ ab_idx,       // MODE0 only
            const unsigned short* __restrict__ w1img,
            const unsigned short* __restrict__ w2img,
            float* __restrict__ outp,
            int n_rows)
{
    extern __shared__ __align__(16) char smem[];
    const uint32_t sb = smem_u32(smem);
    float* bias1  = (float*)(smem + SM_B1);
    float* bias2  = (float*)(smem + SM_B2);
    float* colsum = (float*)(smem + SM_CS);

    const int tid = threadIdx.x, wid = tid >> 5, lane = tid & 31;
    const int n_tiles = (n_rows + 15) >> 4;   // 16-row tiles

    // ---- one-time staging: weights (padded stride), biases, colsum ----
    for (int i = tid; i < 4096; i += 256) {               // W1T: 128 rows x 32 uint4
        int r = i >> 5, c = i & 31;
        *(uint4*)(smem + SM_W1 + r * ASTRIDE + c * 16) = ((const uint4*)w1img)[i];
    }
    for (int i = tid; i < 1024; i += 256) {               // W2T: 64 rows x 16 uint4
        int r = i >> 4, c = i & 15;
        *(uint4*)(smem + SM_W2 + r * HSTRIDE + c * 16) = ((const uint4*)w2img)[i];
    }
    if (tid < HID)  bias1[tid] = b1[tid];
    if (tid < FDIM) { bias2[tid] = b2[tid]; colsum[tid] = 0.f; }

    // static seg3 (global features, identical every tile): write once.
    {
        int r = lane >> 1, h = lane & 1;
        char* dst = smem + SM_A + (wid * 16 + r) * ASTRIDE + 384 + h * 64;
        const uint4* src = (const uint4*)((const char*)g_h_dev + h * 64);
        ((uint4*)dst)[0] = src[0]; ((uint4*)dst)[1] = src[1];
        ((uint4*)dst)[2] = src[2]; ((uint4*)dst)[3] = src[3];
    }

    // ldmatrix lane-address components
    const uint32_t aBase1 = sb + SM_A + (uint32_t)(wid * 16 + (lane & 15)) * ASTRIDE
                            + (uint32_t)(lane >> 4) * 16;
    const uint32_t bN = (uint32_t)((lane & 7) + ((lane >> 4) << 3));
    const uint32_t bK = (uint32_t)(((lane >> 3) & 1) * 16);
    const uint32_t bBase1 = sb + SM_W1 + bN * ASTRIDE + bK;
    const uint32_t bBase2 = sb + SM_W2 + bN * HSTRIDE + bK;

    float ls[8][2];
#pragma unroll
    for (int nb = 0; nb < 8; nb++) { ls[nb][0] = 0.f; ls[nb][1] = 0.f; }

    // async gather for one 16-row warp tile (2 threads per row)
    auto gather_async = [&](int t) {
        int r = lane >> 1, hsel = lane & 1;
        int gr = t * 16 + r;
        int grc = gr < n_rows ? gr : n_rows - 1;
        const uint32_t arow = sb + SM_A + (uint32_t)(wid * 16 + r) * ASTRIDE;
        const uint32_t rrow = sb + SM_RES + (uint32_t)(wid * 16 + r) * 256;
        const char* resrc = (const char*)(resid_glob + (size_t)grc * FDIM);
        if (MODE == 0) {
            if (hsel == 0) {
                const char* s0 = (const char*)(g_atom_h + (size_t)ab_idx[2 * grc] * FDIM);
#pragma unroll
                for (int q = 0; q < 8; q++) cpa16(arow + q * 16, s0 + q * 16);
#pragma unroll
                for (int q = 0; q < 8; q++) cpa16(rrow + q * 16, resrc + q * 16);
            } else {
                const char* s1 = (const char*)(g_atom_h + (size_t)ab_idx[2 * grc + 1] * FDIM);
#pragma unroll
                for (int q = 0; q < 8; q++) cpa16(arow + 128 + q * 16, s1 + q * 16);
#pragma unroll
                for (int q = 0; q < 8; q++) cpa16(rrow + 128 + q * 16, resrc + 128 + q * 16);
            }
        } else {
            if (hsel == 0) {
                const char* s0 = (const char*)(g_atom_h + (size_t)grc * FDIM);
#pragma unroll
                for (int q = 0; q < 8; q++) cpa16(arow + q * 16, s0 + q * 16);
#pragma unroll
                for (int q = 0; q < 8; q++) cpa16(arow + 256 + q * 16, s0 + q * 16);
#pragma unroll
                for (int q = 0; q < 8; q++) cpa16(rrow + q * 16, resrc + q * 16);
            } else {
                const char* s1 = (const char*)(g_agg_h + (size_t)grc * FDIM);
#pragma unroll
                for (int q = 0; q < 8; q++) cpa16(arow + 128 + q * 16, s1 + q * 16);
#pragma unroll
                for (int q = 0; q < 8; q++) cpa16(rrow + 128 + q * 16, resrc + 128 + q * 16);
            }
        }
    };

    const int stride = (int)gridDim.x * 8;
    int tile = blockIdx.x * 8 + wid;
    if (tile < n_tiles) gather_async(tile);
    __syncthreads();                       // weights/bias staged (once)

    for (; tile < n_tiles; tile += stride) {
        const int row_base = tile * 16;
        cpa_wait_all();
        __syncwarp();                      // A seg0/1(,2) + RES landed for whole warp

        // ---- MODE0: convert RES fp32 bond row -> A seg2 fp16 (warp-local) ----
        if (MODE == 0) {
            int r = lane >> 1, h = lane & 1;
            const float4* src = (const float4*)(smem + SM_RES + (wid * 16 + r) * 256 + h * 128);
            uint4* dst = (uint4*)(smem + SM_A + (wid * 16 + r) * ASTRIDE + 256 + h * 64);
#pragma unroll
            for (int q = 0; q < 2; q++) {
                float4 v0 = src[4 * q + 0], v1 = src[4 * q + 1];
                float4 v2 = src[4 * q + 2], v3 = src[4 * q + 3];
                dst[2 * q + 0] = make_uint4(pack_h2(v0.x, v0.y), pack_h2(v0.z, v0.w),
                                            pack_h2(v1.x, v1.y), pack_h2(v1.z, v1.w));
                dst[2 * q + 1] = make_uint4(pack_h2(v2.x, v2.y), pack_h2(v2.z, v2.w),
                                            pack_h2(v3.x, v3.y), pack_h2(v3.z, v3.w));
            }
            __syncwarp();
        }

        // ---- layer 1: 16 rows x 128 cols, K=256 — full N per warp ----
        float c1[16][4];
#pragma unroll
        for (int nb = 0; nb < 16; nb++)
#pragma unroll
            for (int j = 0; j < 4; j++) c1[nb][j] = 0.f;

#pragma unroll
        for (int k0 = 0; k0 < 256; k0 += 16) {
            uint32_t a[4];
            ldm_x4(a, aBase1 + k0 * 2);
#pragma unroll
            for (int g = 0; g < 8; g++) {
                uint32_t bf[4];
                ldm_x4(bf, bBase1 + (uint32_t)(g * 16) * ASTRIDE + k0 * 2);
                mma16816(c1[2 * g],     a, bf[0], bf[1]);
                mma16816(c1[2 * g + 1], a, bf[2], bf[3]);
            }
        }

        // ---- bias + softplus in registers; D-frag -> layer2 A-frag ----
        uint32_t hA[16], hB[16];    // rows lane>>2 / +8, k = nb*8 + (lane&3)*2
#pragma unroll
        for (int nb = 0; nb < 16; nb++) {
            int col = nb * 8 + (lane & 3) * 2;
            float b0v = bias1[col], b1v = bias1[col + 1];
            hA[nb] = pack_h2(softplus_f(c1[nb][0] + b0v), softplus_f(c1[nb][1] + b1v));
            hB[nb] = pack_h2(softplus_f(c1[nb][2] + b0v), softplus_f(c1[nb][3] + b1v));
        }

        // ---- pull residuals for this tile into regs (frees RES for prefetch) ----
        float2 rv0[8], rv1[8];
        {
            int r0 = lane >> 2;
            const char* resbase = smem + SM_RES + (wid * 16) * 256;
#pragma unroll
            for (int nb = 0; nb < 8; nb++) {
                int col = nb * 8 + (lane & 3) * 2;
                rv0[nb] = *(const float2*)(resbase + r0 * 256 + col * 4);
                rv1[nb] = *(const float2*)(resbase + (r0 + 8) * 256 + col * 4);
            }
        }
        __syncwarp();                      // all lanes done reading A/RES

        // ---- prefetch next tile (overlaps layer2 + epilogue) ----
        if (tile + stride < n_tiles) gather_async(tile + stride);

        // ---- layer 2: 16 rows x 64 cols, K=128, A from registers ----
        float c2[8][4];
#pragma unroll
        for (int nb = 0; nb < 8; nb++)
#pragma unroll
            for (int j = 0; j < 4; j++) c2[nb][j] = 0.f;

#pragma unroll
        for (int k0b = 0; k0b < 8; k0b++) {
            uint32_t a2[4] = { hA[2 * k0b], hB[2 * k0b], hA[2 * k0b + 1], hB[2 * k0b + 1] };
#pragma unroll
            for (int g2 = 0; g2 < 4; g2++) {
                uint32_t bf[4];
                ldm_x4(bf, bBase2 + (uint32_t)(g2 * 16) * HSTRIDE + k0b * 32);
                mma16816(c2[2 * g2],     a2, bf[0], bf[1]);
                mma16816(c2[2 * g2 + 1], a2, bf[2], bf[3]);
            }
        }

        // ---- epilogue: bias + residual + stores + running column sums ----
#pragma unroll
        for (int r = 0; r < 2; r++) {
            int grow = row_base + (lane >> 2) + r * 8;
            if (grow < n_rows) {
#pragma unroll
                for (int nb = 0; nb < 8; nb++) {
                    int col = nb * 8 + (lane & 3) * 2;
                    float2 rv = r ? rv1[nb] : rv0[nb];
                    float v0 = c2[nb][r * 2 + 0] + bias2[col]     + rv.x;
                    float v1 = c2[nb][r * 2 + 1] + bias2[col + 1] + rv.y;
                    *(float2*)&outp[(size_t)grow * FDIM + col] = make_float2(v0, v1);
                    if (MODE == 0)
                        ((uint32_t*)g_bond_h)[(size_t)grow * 32 + (col >> 1)] = pack_h2(v0, v1);
                    ls[nb][0] += v0; ls[nb][1] += v1;
                }
            }
        }
    }

    // ---- flush column sums ----
#pragma unroll
    for (int nb = 0; nb < 8; nb++) {
        int col = nb * 8 + (lane & 3) * 2;
        atomicAdd(&colsum[col],     ls[nb][0]);
        atomicAdd(&colsum[col + 1], ls[nb][1]);
    }
    __syncthreads();
    if (tid < FDIM) {
        float* gsum = (MODE == 0) ? g_bond_sum : g_atom_sum;
        atomicAdd(&gsum[tid], colsum[tid]);
    }
}

// ---------------- bond -> atom masked mean aggregation (fp16 in/out) -------
__global__ void agg_kernel(const int* __restrict__ bai, int n_atoms, int max_deg)
{
    int warp = (blockIdx.x * blockDim.x + threadIdx.x) >> 5;
    int lane = threadIdx.x & 31;
    if (warp >= n_atoms) return;
    int myidx = (lane < max_deg) ? bai[(size_t)warp * max_deg + lane] : -1;
    unsigned mb = __ballot_sync(0xffffffffu, myidx >= 0);
    int cnt = __popc(mb);
    float sx = 0.f, sy = 0.f;
#pragma unroll
    for (int d = 0; d < 32; d += 8) {
        if (d >= max_deg) break;
        int i0 = __shfl_sync(0xffffffffu, myidx, d + 0);
        int i1 = __shfl_sync(0xffffffffu, myidx, d + 1);
        int i2 = __shfl_sync(0xffffffffu, myidx, d + 2);
        int i3 = __shfl_sync(0xffffffffu, myidx, d + 3);
        int i4 = __shfl_sync(0xffffffffu, myidx, d + 4);
        int i5 = __shfl_sync(0xffffffffu, myidx, d + 5);
        int i6 = __shfl_sync(0xffffffffu, myidx, d + 6);
        int i7 = __shfl_sync(0xffffffffu, myidx, d + 7);
        int ids[8] = {i0, i1, i2, i3, i4, i5, i6, i7};
#pragma unroll
        for (int q = 0; q < 8; q++) {
            if (d + q < max_deg && ids[q] >= 0) {
                uint32_t u = ((const uint32_t*)g_bond_h)[(size_t)ids[q] * 32 + lane];
                float2 v = __half22float2(*(__half2*)&u);
                sx += v.x; sy += v.y;
            }
        }
    }
    float inv = 1.f / fmaxf((float)cnt, 1.f);
    ((uint32_t*)g_agg_h)[(size_t)warp * 32 + lane] = pack_h2(sx * inv, sy * inv);
}

// ---------------- global MLP ----------------
__global__ void global_kernel(const float* __restrict__ gfeat,
                              const float* __restrict__ Wg1, const float* __restrict__ bg1,
                              const float* __restrict__ Wg2, const float* __restrict__ bg2,
                              float* __restrict__ outg,
                              float n_atoms_f, float n_bonds_f)
{
    __shared__ float comb[3 * FDIM];
    __shared__ float h[HID];
    int t = threadIdx.x;  // 192 threads
    if (t < FDIM)            comb[t] = g_atom_sum[t] / n_atoms_f;
    else if (t < 2 * FDIM)   comb[t] = g_bond_sum[t - FDIM] / n_bonds_f;
    else if (t < 3 * FDIM)   comb[t] = gfeat[t - 2 * FDIM];
    __syncthreads();
    if (t < HID) {
        float a = bg1[t];
#pragma unroll 4
        for (int k = 0; k < 3 * FDIM; k++) a += comb[k] * Wg1[(size_t)k * HID + t];
        h[t] = softplus_f(a);
    }
    __syncthreads();
    if (t < FDIM) {
        float a = bg2[t] + gfeat[t];
#pragma unroll 4
        for (int k = 0; k < HID; k++) a += h[k] * Wg2[(size_t)k * FDIM + t];
        outg[t] = a;
    }
}

// ---------------- launch ----------------
extern "C" void kernel_launch(void* const* d_in, const int* in_sizes, int n_in,
                              void* d_out, int out_size)
{
    const float* atom_f = (const float*)d_in[0];
    const float* bond_f = (const float*)d_in[1];
    const float* gfeat  = (const float*)d_in[2];
    const float* Wb1 = (const float*)d_in[3];
    const float* bb1 = (const float*)d_in[4];
    const float* Wb2 = (const float*)d_in[5];
    const float* bb2 = (const float*)d_in[6];
    const float* Wa1 = (const float*)d_in[7];
    const float* ba1 = (const float*)d_in[8];
    const float* Wa2 = (const float*)d_in[9];
    const float* ba2 = (const float*)d_in[10];
    const float* Wg1 = (const float*)d_in[11];
    const float* bg1 = (const float*)d_in[12];
    const float* Wg2 = (const float*)d_in[13];
    const float* bg2 = (const float*)d_in[14];
    const int* ab_idx = (const int*)d_in[15];
    const int* ba_idx = (const int*)d_in[16];

    const int n_atoms = in_sizes[0] / FDIM;
    const int n_bonds = in_sizes[1] / FDIM;
    const int max_deg = in_sizes[16] / n_atoms;

    float* out       = (float*)d_out;
    float* out_atoms = out;
    float* out_bonds = out + (size_t)n_atoms * FDIM;
    float* out_glob  = out + (size_t)n_atoms * FDIM + (size_t)n_bonds * FDIM;

    cudaFuncSetAttribute(mlp_tc<0>, cudaFuncAttributeMaxDynamicSharedMemorySize, SMEM_SZ);
    cudaFuncSetAttribute(mlp_tc<1>, cudaFuncAttributeMaxDynamicSharedMemorySize, SMEM_SZ);

    unsigned short *pwb1, *pwb2, *pwa1, *pwa2;
    cudaGetSymbolAddress((void**)&pwb1, wb1_img);
    cudaGetSymbolAddress((void**)&pwb2, wb2_img);
    cudaGetSymbolAddress((void**)&pwa1, wa1_img);
    cudaGetSymbolAddress((void**)&pwa2, wa2_img);

    int nsm = 148;
    cudaDeviceGetAttribute(&nsm, cudaDevAttrMultiProcessorCount, 0);

    init_kernel<<<1, 128>>>();

    const int prep_elems = HID * 4 * FDIM + FDIM * HID;
    prep_weights<<<(prep_elems + 255) / 256, 256>>>(Wb1, Wb2, pwb1, pwb2);
    prep_weights<<<(prep_elems + 255) / 256, 256>>>(Wa1, Wa2, pwa1, pwa2);

    const int n4 = n_atoms * (FDIM / 4);
    prep_atom<<<(n4 + 255) / 256, 256>>>(atom_f, gfeat, n4);

    const int bond_tiles16 = (n_bonds + 15) / 16;
    int grid0 = nsm < (bond_tiles16 + 7) / 8 ? nsm : (bond_tiles16 + 7) / 8;
    if (grid0 < 1) grid0 = 1;
    mlp_tc<0><<<grid0, 256, SMEM_SZ>>>(
        bond_f, bb1, bb2, ab_idx, pwb1, pwb2, out_bonds, n_bonds);

    const int agg_blocks = ((n_atoms * 32) + 255) / 256;
    agg_kernel<<<agg_blocks, 256>>>(ba_idx, n_atoms, max_deg);

    const int atom_tiles16 = (n_atoms + 15) / 16;
    int grid1 = nsm < (atom_tiles16 + 7) / 8 ? nsm : (atom_tiles16 + 7) / 8;
    if (grid1 < 1) grid1 = 1;
    mlp_tc<1><<<grid1, 256, SMEM_SZ>>>(
        atom_f, ba1, ba2, nullptr, pwa1, pwa2, out_atoms, n_atoms);

    global_kernel<<<1, 192>>>(gfeat, Wg1, bg1, Wg2, bg2, out_glob,
                              (float)n_atoms, (float)n_bonds);
}

// round 16
// speedup vs baseline: 1.2783x; 1.0873x over previous
#include <cuda_runtime.h>
#include <cuda_fp16.h>
#include <math.h>
#include <stdint.h>

#define FDIM 64
#define HID  128
#define N_ATOMS_MAX 100000
#define N_BONDS_MAX 800000
#define NWARP 12
#define NTHREAD (NWARP * 32)

// ---------------- device scratch (no allocs allowed) ----------------
__device__ float g_bond_sum[FDIM];
__device__ float g_atom_sum[FDIM];
__device__ __align__(16) unsigned short g_atom_h[(size_t)N_ATOMS_MAX * FDIM]; // fp16 atom feats
__device__ __align__(16) unsigned short g_agg_h [(size_t)N_ATOMS_MAX * FDIM]; // fp16 agg
__device__ __align__(16) unsigned short g_bond_h[(size_t)N_BONDS_MAX * FDIM]; // fp16 updated bonds
__device__ __align__(16) unsigned short g_h_dev[FDIM];                        // fp16 global feats
// pre-transposed fp16 weight images: W^T stored [N][K] row-major
__device__ __align__(16) unsigned short wb1_img[HID * 4 * FDIM];   // [128][256]
__device__ __align__(16) unsigned short wb2_img[FDIM * HID];       // [64][128]
__device__ __align__(16) unsigned short wa1_img[HID * 4 * FDIM];
__device__ __align__(16) unsigned short wa2_img[FDIM * HID];

// ---------------- helpers ----------------
__device__ __forceinline__ float softplus_f(float x) {
    float t = __expf(-fabsf(x));
    return fmaxf(x, 0.f) + __logf(1.f + t);
}
__device__ __forceinline__ uint32_t pack_h2(float a, float b) {
    __half2 h = __floats2half2_rn(a, b);
    return *(uint32_t*)&h;
}
__device__ __forceinline__ uint32_t smem_u32(const void* p) {
    uint32_t a;
    asm("{ .reg .u64 t; cvta.to.shared.u64 t, %1; cvt.u32.u64 %0, t; }"
        : "=r"(a) : "l"(p));
    return a;
}
__device__ __forceinline__ void ldm_x4(uint32_t (&r)[4], uint32_t addr) {
    asm volatile("ldmatrix.sync.aligned.m8n8.x4.shared.b16 {%0,%1,%2,%3}, [%4];"
                 : "=r"(r[0]), "=r"(r[1]), "=r"(r[2]), "=r"(r[3]) : "r"(addr));
}
__device__ __forceinline__ void mma16816(float (&d)[4], const uint32_t (&a)[4],
                                         uint32_t b0, uint32_t b1) {
    asm volatile("mma.sync.aligned.m16n8k16.row.col.f32.f16.f16.f32 "
                 "{%0,%1,%2,%3}, {%4,%5,%6,%7}, {%8,%9}, {%0,%1,%2,%3};"
                 : "+f"(d[0]), "+f"(d[1]), "+f"(d[2]), "+f"(d[3])
                 : "r"(a[0]), "r"(a[1]), "r"(a[2]), "r"(a[3]), "r"(b0), "r"(b1));
}
__device__ __forceinline__ void cpa16(uint32_t dst, const void* src) {
    asm volatile("cp.async.ca.shared.global [%0], [%1], 16;"
                 :: "r"(dst), "l"(src));
}
__device__ __forceinline__ void cpa_wait_all() {
    asm volatile("cp.async.wait_all;" ::: "memory");
}

// ---------------- init ----------------
__global__ void init_kernel() {
    int t = threadIdx.x;
    if (t < FDIM) { g_bond_sum[t] = 0.f; g_atom_sum[t] = 0.f; }
}

// ---------------- weight transpose + fp16 convert ----------------
__global__ void prep_weights(const float* __restrict__ W1, const float* __restrict__ W2,
                             unsigned short* __restrict__ img1,
                             unsigned short* __restrict__ img2) {
    int idx = blockIdx.x * blockDim.x + threadIdx.x;
    if (idx < HID * 4 * FDIM) {                 // W1^T [128][256]
        int n = idx >> 8, k = idx & 255;
        __half h = __float2half_rn(W1[(size_t)k * HID + n]);
        img1[idx] = *(unsigned short*)&h;
    } else if (idx < HID * 4 * FDIM + FDIM * HID) {  // W2^T [64][128]
        int t = idx - HID * 4 * FDIM;
        int n = t >> 7, k = t & 127;
        __half h = __float2half_rn(W2[(size_t)k * FDIM + n]);
        img2[t] = *(unsigned short*)&h;
    }
}

// ---------------- atom features + gfeat -> fp16 ----------------
__global__ void prep_atom(const float* __restrict__ atom_f,
                          const float* __restrict__ gfeat, int n4) {
    int idx = blockIdx.x * blockDim.x + threadIdx.x;
    if (idx < n4) {
        float4 v = ((const float4*)atom_f)[idx];
        uint2 o = make_uint2(pack_h2(v.x, v.y), pack_h2(v.z, v.w));
        ((uint2*)g_atom_h)[idx] = o;
    }
    if (blockIdx.x == 0 && threadIdx.x < 16) {
        float4 v = ((const float4*)gfeat)[threadIdx.x];
        ((uint2*)g_h_dev)[threadIdx.x] = make_uint2(pack_h2(v.x, v.y), pack_h2(v.z, v.w));
    }
}

// ---------------- SMEM layout (bytes) ----------------
static constexpr int ASTRIDE = 528;   // 256+8 halves
static constexpr int HSTRIDE = 272;   // 128+8 halves
static constexpr int SM_A  = 0;                          // NWARP*16 rows
static constexpr int SM_W1 = SM_A + NWARP * 16 * ASTRIDE;    // 101376 -> W1 at 101376
static constexpr int SM_W2 = SM_W1 + 128 * ASTRIDE;          // 168960
static constexpr int SM_B1 = SM_W2 + 64 * HSTRIDE;           // 186368
static constexpr int SM_B2 = SM_B1 + 512;                    // 186880
static constexpr int SM_CS = SM_B2 + 256;                    // 187136
static constexpr int SMEM_SZ = SM_CS + 256;                  // 187392

// ---------------- persistent fused 2-layer MLP (mma.sync) ----------------
// Fully warp-independent: each of 12 warps owns a 16-row tile stream; the
// softplus'd hidden stays in registers (layer1 D-frag == layer2 A-frag).
// No CTA barriers in the main loop. 3 warps/SMSP for latency hiding.
// MODE 0 (bonds): comb = [atom_h[i], atom_h[j], f16(bond_f[row]), g_h]
// MODE 1 (atoms): comb = [atom_h[row], agg_h[row], atom_h[row], g_h]
template <int MODE>
__global__ __launch_bounds__(NTHREAD, 1)
void mlp_tc(const float* __restrict__ resid_glob,   // MODE1: atom_f; MODE0: bond_f
            const float* __restrict__ b1, const float* __restrict__ b2,
            const int*   __restrict__ ab_idx,       // MODE0 only
            const unsigned short* __restrict__ w1img,
            const unsigned short* __restrict__ w2img,
            float* __restrict__ outp,
            int n_rows)
{
    extern __shared__ __align__(16) char smem[];
    const uint32_t sb = smem_u32(smem);
    float* bias1  = (float*)(smem + SM_B1);
    float* bias2  = (float*)(smem + SM_B2);
    float* colsum = (float*)(smem + SM_CS);

    const int tid = threadIdx.x, wid = tid >> 5, lane = tid & 31;
    const int n_tiles = (n_rows + 15) >> 4;   // 16-row tiles

    // ---- one-time staging: weights (padded stride), biases, colsum ----
    for (int i = tid; i < 4096; i += NTHREAD) {           // W1T: 128 rows x 32 uint4
        int r = i >> 5, c = i & 31;
        *(uint4*)(smem + SM_W1 + r * ASTRIDE + c * 16) = ((const uint4*)w1img)[i];
    }
    for (int i = tid; i < 1024; i += NTHREAD) {           // W2T: 64 rows x 16 uint4
        int r = i >> 4, c = i & 15;
        *(uint4*)(smem + SM_W2 + r * HSTRIDE + c * 16) = ((const uint4*)w2img)[i];
    }
    if (tid < HID)  bias1[tid] = b1[tid];
    if (tid < FDIM) { bias2[tid] = b2[tid]; colsum[tid] = 0.f; }

    // static seg3 (global features, identical every tile): write once.
    {
        int r = lane >> 1, h = lane & 1;
        char* dst = smem + SM_A + (wid * 16 + r) * ASTRIDE + 384 + h * 64;
        const uint4* src = (const uint4*)((const char*)g_h_dev + h * 64);
        ((uint4*)dst)[0] = src[0]; ((uint4*)dst)[1] = src[1];
        ((uint4*)dst)[2] = src[2]; ((uint4*)dst)[3] = src[3];
    }

    // ldmatrix lane-address components
    const uint32_t aBase1 = sb + SM_A + (uint32_t)(wid * 16 + (lane & 15)) * ASTRIDE
                            + (uint32_t)(lane >> 4) * 16;
    const uint32_t bN = (uint32_t)((lane & 7) + ((lane >> 4) << 3));
    const uint32_t bK = (uint32_t)(((lane >> 3) & 1) * 16);
    const uint32_t bBase1 = sb + SM_W1 + bN * ASTRIDE + bK;
    const uint32_t bBase2 = sb + SM_W2 + bN * HSTRIDE + bK;

    float ls[8][2];
#pragma unroll
    for (int nb = 0; nb < 8; nb++) { ls[nb][0] = 0.f; ls[nb][1] = 0.f; }

    // async gather of fp16 segments for one 16-row warp tile (2 threads/row)
    auto gather_async = [&](int t) {
        int r = lane >> 1, hsel = lane & 1;
        int gr = t * 16 + r;
        int grc = gr < n_rows ? gr : n_rows - 1;
        const uint32_t arow = sb + SM_A + (uint32_t)(wid * 16 + r) * ASTRIDE;
        if (MODE == 0) {
            if (hsel == 0) {
                const char* s0 = (const char*)(g_atom_h + (size_t)ab_idx[2 * grc] * FDIM);
#pragma unroll
                for (int q = 0; q < 8; q++) cpa16(arow + q * 16, s0 + q * 16);
            } else {
                const char* s1 = (const char*)(g_atom_h + (size_t)ab_idx[2 * grc + 1] * FDIM);
#pragma unroll
                for (int q = 0; q < 8; q++) cpa16(arow + 128 + q * 16, s1 + q * 16);
            }
        } else {
            if (hsel == 0) {
                const char* s0 = (const char*)(g_atom_h + (size_t)grc * FDIM);
#pragma unroll
                for (int q = 0; q < 8; q++) cpa16(arow + q * 16, s0 + q * 16);
#pragma unroll
                for (int q = 0; q < 8; q++) cpa16(arow + 256 + q * 16, s0 + q * 16);
            } else {
                const char* s1 = (const char*)(g_agg_h + (size_t)grc * FDIM);
#pragma unroll
                for (int q = 0; q < 8; q++) cpa16(arow + 128 + q * 16, s1 + q * 16);
            }
        }
    };

    const int stride = (int)gridDim.x * NWARP;
    int tile = blockIdx.x * NWARP + wid;
    if (tile < n_tiles) gather_async(tile);
    __syncthreads();                       // weights/bias staged (once)

    for (; tile < n_tiles; tile += stride) {
        const int row_base = tile * 16;

        // ---- MODE0: LDG bond fp32 half-row, convert -> A seg2 fp16 ----
        if (MODE == 0) {
            int r = lane >> 1, h = lane & 1;
            int gr = row_base + r;
            int grc = gr < n_rows ? gr : n_rows - 1;
            const float4* src = (const float4*)(resid_glob + (size_t)grc * FDIM) + h * 8;
            uint4* dst = (uint4*)(smem + SM_A + (wid * 16 + r) * ASTRIDE + 256 + h * 64);
#pragma unroll
            for (int q = 0; q < 2; q++) {
                float4 v0 = src[4 * q + 0], v1 = src[4 * q + 1];
                float4 v2 = src[4 * q + 2], v3 = src[4 * q + 3];
                dst[2 * q + 0] = make_uint4(pack_h2(v0.x, v0.y), pack_h2(v0.z, v0.w),
                                            pack_h2(v1.x, v1.y), pack_h2(v1.z, v1.w));
                dst[2 * q + 1] = make_uint4(pack_h2(v2.x, v2.y), pack_h2(v2.z, v2.w),
                                            pack_h2(v3.x, v3.y), pack_h2(v3.z, v3.w));
            }
        }
        cpa_wait_all();
        __syncwarp();                      // A segments landed for whole warp

        // ---- layer 1: 16 rows x 128 cols, K=256 — full N per warp ----
        float c1[16][4];
#pragma unroll
        for (int nb = 0; nb < 16; nb++)
#pragma unroll
            for (int j = 0; j < 4; j++) c1[nb][j] = 0.f;

#pragma unroll
        for (int k0 = 0; k0 < 256; k0 += 16) {
            uint32_t a[4];
            ldm_x4(a, aBase1 + k0 * 2);
#pragma unroll
            for (int g = 0; g < 8; g++) {
                uint32_t bf[4];
                ldm_x4(bf, bBase1 + (uint32_t)(g * 16) * ASTRIDE + k0 * 2);
                mma16816(c1[2 * g],     a, bf[0], bf[1]);
                mma16816(c1[2 * g + 1], a, bf[2], bf[3]);
            }
        }

        // ---- bias + softplus in registers; D-frag -> layer2 A-frag ----
        uint32_t hA[16], hB[16];    // rows lane>>2 / +8, k = nb*8 + (lane&3)*2
#pragma unroll
        for (int nb = 0; nb < 16; nb++) {
            int col = nb * 8 + (lane & 3) * 2;
            float b0v = bias1[col], b1v = bias1[col + 1];
            hA[nb] = pack_h2(softplus_f(c1[nb][0] + b0v), softplus_f(c1[nb][1] + b1v));
            hB[nb] = pack_h2(softplus_f(c1[nb][2] + b0v), softplus_f(c1[nb][3] + b1v));
        }
        __syncwarp();                      // all lanes done reading A

        // ---- prefetch next tile's fp16 segments (overlaps layer2) ----
        if (tile + stride < n_tiles) gather_async(tile + stride);

        // ---- prefetch residual float2s (epilogue fragment layout) ----
        float2 rv0[8], rv1[8];
        {
            int r0 = row_base + (lane >> 2);
            int r1 = r0 + 8;
            int r0c = r0 < n_rows ? r0 : n_rows - 1;
            int r1c = r1 < n_rows ? r1 : n_rows - 1;
            const float* p0 = resid_glob + (size_t)r0c * FDIM + (lane & 3) * 2;
            const float* p1 = resid_glob + (size_t)r1c * FDIM + (lane & 3) * 2;
#pragma unroll
            for (int nb = 0; nb < 8; nb++) {
                rv0[nb] = *(const float2*)(p0 + nb * 8);
                rv1[nb] = *(const float2*)(p1 + nb * 8);
            }
        }

        // ---- layer 2: 16 rows x 64 cols, K=128, A from registers ----
        float c2[8][4];
#pragma unroll
        for (int nb = 0; nb < 8; nb++)
#pragma unroll
            for (int j = 0; j < 4; j++) c2[nb][j] = 0.f;

#pragma unroll
        for (int k0b = 0; k0b < 8; k0b++) {
            uint32_t a2[4] = { hA[2 * k0b], hB[2 * k0b], hA[2 * k0b + 1], hB[2 * k0b + 1] };
#pragma unroll
            for (int g2 = 0; g2 < 4; g2++) {
                uint32_t bf[4];
                ldm_x4(bf, bBase2 + (uint32_t)(g2 * 16) * HSTRIDE + k0b * 32);
                mma16816(c2[2 * g2],     a2, bf[0], bf[1]);
                mma16816(c2[2 * g2 + 1], a2, bf[2], bf[3]);
            }
        }

        // ---- epilogue: bias + residual + stores + running column sums ----
#pragma unroll
        for (int r = 0; r < 2; r++) {
            int grow = row_base + (lane >> 2) + r * 8;
            if (grow < n_rows) {
#pragma unroll
                for (int nb = 0; nb < 8; nb++) {
                    int col = nb * 8 + (lane & 3) * 2;
                    float2 rv = r ? rv1[nb] : rv0[nb];
                    float v0 = c2[nb][r * 2 + 0] + bias2[col]     + rv.x;
                    float v1 = c2[nb][r * 2 + 1] + bias2[col + 1] + rv.y;
                    *(float2*)&outp[(size_t)grow * FDIM + col] = make_float2(v0, v1);
                    if (MODE == 0)
                        ((uint32_t*)g_bond_h)[(size_t)grow * 32 + (col >> 1)] = pack_h2(v0, v1);
                    ls[nb][0] += v0; ls[nb][1] += v1;
                }
            }
        }
    }

    // ---- flush column sums ----
#pragma unroll
    for (int nb = 0; nb < 8; nb++) {
        int col = nb * 8 + (lane & 3) * 2;
        atomicAdd(&colsum[col],     ls[nb][0]);
        atomicAdd(&colsum[col + 1], ls[nb][1]);
    }
    __syncthreads();
    if (tid < FDIM) {
        float* gsum = (MODE == 0) ? g_bond_sum : g_atom_sum;
        atomicAdd(&gsum[tid], colsum[tid]);
    }
}

// ---------------- bond -> atom masked mean aggregation (fp16 in/out) -------
__global__ void agg_kernel(const int* __restrict__ bai, int n_atoms, int max_deg)
{
    int warp = (blockIdx.x * blockDim.x + threadIdx.x) >> 5;
    int lane = threadIdx.x & 31;
    if (warp >= n_atoms) return;
    int myidx = (lane < max_deg) ? bai[(size_t)warp * max_deg + lane] : -1;
    unsigned mb = __ballot_sync(0xffffffffu, myidx >= 0);
    int cnt = __popc(mb);
    float sx = 0.f, sy = 0.f;
#pragma unroll
    for (int d = 0; d < 32; d += 8) {
        if (d >= max_deg) break;
        int i0 = __shfl_sync(0xffffffffu, myidx, d + 0);
        int i1 = __shfl_sync(0xffffffffu, myidx, d + 1);
        int i2 = __shfl_sync(0xffffffffu, myidx, d + 2);
        int i3 = __shfl_sync(0xffffffffu, myidx, d + 3);
        int i4 = __shfl_sync(0xffffffffu, myidx, d + 4);
        int i5 = __shfl_sync(0xffffffffu, myidx, d + 5);
        int i6 = __shfl_sync(0xffffffffu, myidx, d + 6);
        int i7 = __shfl_sync(0xffffffffu, myidx, d + 7);
        int ids[8] = {i0, i1, i2, i3, i4, i5, i6, i7};
#pragma unroll
        for (int q = 0; q < 8; q++) {
            if (d + q < max_deg && ids[q] >= 0) {
                uint32_t u = ((const uint32_t*)g_bond_h)[(size_t)ids[q] * 32 + lane];
                float2 v = __half22float2(*(__half2*)&u);
                sx += v.x; sy += v.y;
            }
        }
    }
    float inv = 1.f / fmaxf((float)cnt, 1.f);
    ((uint32_t*)g_agg_h)[(size_t)warp * 32 + lane] = pack_h2(sx * inv, sy * inv);
}

// ---------------- global MLP ----------------
__global__ void global_kernel(const float* __restrict__ gfeat,
                              const float* __restrict__ Wg1, const float* __restrict__ bg1,
                              const float* __restrict__ Wg2, const float* __restrict__ bg2,
                              float* __restrict__ outg,
                              float n_atoms_f, float n_bonds_f)
{
    __shared__ float comb[3 * FDIM];
    __shared__ float h[HID];
    int t = threadIdx.x;  // 192 threads
    if (t < FDIM)            comb[t] = g_atom_sum[t] / n_atoms_f;
    else if (t < 2 * FDIM)   comb[t] = g_bond_sum[t - FDIM] / n_bonds_f;
    else if (t < 3 * FDIM)   comb[t] = gfeat[t - 2 * FDIM];
    __syncthreads();
    if (t < HID) {
        float a = bg1[t];
#pragma unroll 4
        for (int k = 0; k < 3 * FDIM; k++) a += comb[k] * Wg1[(size_t)k * HID + t];
        h[t] = softplus_f(a);
    }
    __syncthreads();
    if (t < FDIM) {
        float a = bg2[t] + gfeat[t];
#pragma unroll 4
        for (int k = 0; k < HID; k++) a += h[k] * Wg2[(size_t)k * FDIM + t];
        outg[t] = a;
    }
}

// ---------------- launch ----------------
extern "C" void kernel_launch(void* const* d_in, const int* in_sizes, int n_in,
                              void* d_out, int out_size)
{
    const float* atom_f = (const float*)d_in[0];
    const float* bond_f = (const float*)d_in[1];
    const float* gfeat  = (const float*)d_in[2];
    const float* Wb1 = (const float*)d_in[3];
    const float* bb1 = (const float*)d_in[4];
    const float* Wb2 = (const float*)d_in[5];
    const float* bb2 = (const float*)d_in[6];
    const float* Wa1 = (const float*)d_in[7];
    const float* ba1 = (const float*)d_in[8];
    const float* Wa2 = (const float*)d_in[9];
    const float* ba2 = (const float*)d_in[10];
    const float* Wg1 = (const float*)d_in[11];
    const float* bg1 = (const float*)d_in[12];
    const float* Wg2 = (const float*)d_in[13];
    const float* bg2 = (const float*)d_in[14];
    const int* ab_idx = (const int*)d_in[15];
    const int* ba_idx = (const int*)d_in[16];

    const int n_atoms = in_sizes[0] / FDIM;
    const int n_bonds = in_sizes[1] / FDIM;
    const int max_deg = in_sizes[16] / n_atoms;

    float* out       = (float*)d_out;
    float* out_atoms = out;
    float* out_bonds = out + (size_t)n_atoms * FDIM;
    float* out_glob  = out + (size_t)n_atoms * FDIM + (size_t)n_bonds * FDIM;

    cudaFuncSetAttribute(mlp_tc<0>, cudaFuncAttributeMaxDynamicSharedMemorySize, SMEM_SZ);
    cudaFuncSetAttribute(mlp_tc<1>, cudaFuncAttributeMaxDynamicSharedMemorySize, SMEM_SZ);

    unsigned short *pwb1, *pwb2, *pwa1, *pwa2;
    cudaGetSymbolAddress((void**)&pwb1, wb1_img);
    cudaGetSymbolAddress((void**)&pwb2, wb2_img);
    cudaGetSymbolAddress((void**)&pwa1, wa1_img);
    cudaGetSymbolAddress((void**)&pwa2, wa2_img);

    int nsm = 148;
    cudaDeviceGetAttribute(&nsm, cudaDevAttrMultiProcessorCount, 0);

    init_kernel<<<1, 128>>>();

    const int prep_elems = HID * 4 * FDIM + FDIM * HID;
    prep_weights<<<(prep_elems + 255) / 256, 256>>>(Wb1, Wb2, pwb1, pwb2);
    prep_weights<<<(prep_elems + 255) / 256, 256>>>(Wa1, Wa2, pwa1, pwa2);

    const int n4 = n_atoms * (FDIM / 4);
    prep_atom<<<(n4 + 255) / 256, 256>>>(atom_f, gfeat, n4);

    const int bond_tiles16 = (n_bonds + 15) / 16;
    int g0 = (bond_tiles16 + NWARP - 1) / NWARP;
    int grid0 = nsm < g0 ? nsm : g0;
    if (grid0 < 1) grid0 = 1;
    mlp_tc<0><<<grid0, NTHREAD, SMEM_SZ>>>(
        bond_f, bb1, bb2, ab_idx, pwb1, pwb2, out_bonds, n_bonds);

    const int agg_blocks = ((n_atoms * 32) + 255) / 256;
    agg_kernel<<<agg_blocks, 256>>>(ba_idx, n_atoms, max_deg);

    const int atom_tiles16 = (n_atoms + 15) / 16;
    int g1 = (atom_tiles16 + NWARP - 1) / NWARP;
    int grid1 = nsm < g1 ? nsm : g1;
    if (grid1 < 1) grid1 = 1;
    mlp_tc<1><<<grid1, NTHREAD, SMEM_SZ>>>(
        atom_f, ba1, ba2, nullptr, pwa1, pwa2, out_atoms, n_atoms);

    global_kernel<<<1, 192>>>(gfeat, Wg1, bg1, Wg2, bg2, out_glob,
                              (float)n_atoms, (float)n_bonds);
}